// round 17
// baseline (speedup 1.0000x reference)
#include <cuda_runtime.h>
#include <cuda_fp16.h>
#include <cstdint>

// Problem dims
static constexpr int MDIM = 8192;    // B*S
static constexpr int NDIM = 11008;   // OUT
static constexpr int KDIM = 4096;    // IN

// GEMM tiling (mma.sync path: harness assembles via .target sm_103 -> no tcgen05;
// cp.async.bulk + mbarrier are sm_90 baseline, NOT a-gated)
static constexpr int BM = 128;
static constexpr int BN = 128;
static constexpr int BK = 64;                 // 64 fp16 = 128B rows
static constexpr int NCH = KDIM / BK;         // 64 K-chunks
static constexpr int STAGES = 3;
static constexpr int NTHREADS = 128;          // 4 warps, warp tile 64x64

static constexpr int TILE_BYTES = 128 * 128;  // 16 KB: 128 rows x 128B (swizzled)
static constexpr int SM_A    = 0;             // 3 x 16KB
static constexpr int SM_B    = STAGES * TILE_BYTES;            // 49152
static constexpr int SM_MB   = SM_B + STAGES * TILE_BYTES;     // 98304 (3 x 8B mbars)
static constexpr int SM_END  = SM_MB + 64;
static constexpr int DYN_SMEM = SM_END + 1024;                 // ~97KB -> 2 CTAs/SM

static constexpr int GRID_M = MDIM / BM;      // 64
static constexpr int GRID_N = NDIM / BN;      // 86
static constexpr int TOT_TILES = GRID_M * GRID_N;  // 5504
static constexpr int GROUP_M = 8;             // L2 tile-swizzle panel height
static constexpr int NCTA = 296;              // persistent: 2 per SM x 148

// Pre-tiled, pre-swizzled fp16 copies:
//   g_xh[mtile][kchunk][16KB tile], g_wh[ntile][kchunk][16KB tile]
__device__ __half g_xh[(size_t)MDIM * KDIM];
__device__ __half g_wh[(size_t)NDIM * KDIM];

// ---------------------------------------------------------------- helpers
__device__ __forceinline__ uint32_t smem_u32(const void* p) {
    uint32_t a;
    asm("{ .reg .u64 t; cvta.to.shared.u64 t, %1; cvt.u32.u64 %0, t; }"
        : "=r"(a) : "l"(p));
    return a;
}

__device__ __forceinline__ uint32_t h2_bits(__half2 h) {
    union { __half2 h2; uint32_t u; } cvt;
    cvt.h2 = h;
    return cvt.u;
}

__device__ __forceinline__ void mbar_init(uint32_t addr, uint32_t cnt) {
    asm volatile("mbarrier.init.shared.b64 [%0], %1;" :: "r"(addr), "r"(cnt) : "memory");
}

__device__ __forceinline__ void mbar_expect_tx(uint32_t addr, uint32_t tx) {
    asm volatile("mbarrier.arrive.expect_tx.shared.b64 _, [%0], %1;"
                 :: "r"(addr), "r"(tx) : "memory");
}

__device__ __forceinline__ void mbar_wait(uint32_t addr, uint32_t phase) {
    asm volatile(
        "{\n\t"
        ".reg .pred P;\n\t"
        "WLOOP_%=:\n\t"
        "mbarrier.try_wait.parity.acquire.cta.shared::cta.b64 P, [%0], %1, 0x989680;\n\t"
        "@P bra WDONE_%=;\n\t"
        "bra WLOOP_%=;\n\t"
        "WDONE_%=:\n\t"
        "}"
        :: "r"(addr), "r"(phase) : "memory");
}

// One-instruction bulk copy GMEM -> SMEM, completion via mbarrier tx-count
__device__ __forceinline__ void bulk_ld(uint32_t dst, const void* src,
                                        uint32_t bytes, uint32_t mbar) {
    asm volatile(
        "cp.async.bulk.shared::cluster.global.mbarrier::complete_tx::bytes "
        "[%0], [%1], %2, [%3];"
        :: "r"(dst), "l"(src), "r"(bytes), "r"(mbar) : "memory");
}

__device__ __forceinline__ void ldsm_x4(uint32_t* r, uint32_t addr) {
    asm volatile("ldmatrix.sync.aligned.m8n8.x4.shared.b16 {%0,%1,%2,%3}, [%4];"
                 : "=r"(r[0]), "=r"(r[1]), "=r"(r[2]), "=r"(r[3])
                 : "r"(addr));
}

__device__ __forceinline__ void mma16816(float* c, const uint32_t* a,
                                         uint32_t b0, uint32_t b1) {
    asm volatile(
        "mma.sync.aligned.m16n8k16.row.col.f32.f16.f16.f32 "
        "{%0,%1,%2,%3}, {%4,%5,%6,%7}, {%8,%9}, {%0,%1,%2,%3};"
        : "+f"(c[0]), "+f"(c[1]), "+f"(c[2]), "+f"(c[3])
        : "r"(a[0]), "r"(a[1]), "r"(a[2]), "r"(a[3]), "r"(b0), "r"(b1));
}

// ---------------------------------------------------------------- conversion
// Write fp16 into pre-tiled layout: tile (row>>7, k>>6), inside 128x128B with
// SW swizzle (seg*16 ^ ((row&7)<<4)). Swizzle permutes 16B segs within one
// 128B line, so 8 consecutive threads still write one full 128B line.
__global__ void cvt_x_kernel(const float* __restrict__ x) {
    size_t i = (size_t)blockIdx.x * blockDim.x + threadIdx.x;   // seg index
    size_t nseg = (size_t)MDIM * (KDIM / 8);
    if (i < nseg) {
        int m  = (int)(i >> 9);           // 512 segs per row
        int sk = (int)(i & 511);
        int kc = sk >> 3;
        int seg = sk & 7;
        const float4* src = reinterpret_cast<const float4*>(x + (size_t)m * KDIM + sk * 8);
        float4 v0 = src[0], v1 = src[1];
        uint4 o;
        o.x = h2_bits(__floats2half2_rn(v0.x, v0.y));
        o.y = h2_bits(__floats2half2_rn(v0.z, v0.w));
        o.z = h2_bits(__floats2half2_rn(v1.x, v1.y));
        o.w = h2_bits(__floats2half2_rn(v1.z, v1.w));
        size_t tile = (size_t)(m >> 7) * NCH + kc;
        uint32_t off = (uint32_t)(((m & 127) * 128 + seg * 16) ^ ((m & 7) << 4));
        *reinterpret_cast<uint4*>(
            reinterpret_cast<char*>(g_xh) + tile * TILE_BYTES + off) = o;
    }
}

__global__ void cvt_w_kernel(const int* __restrict__ w4, const float* __restrict__ zp) {
    size_t i = (size_t)blockIdx.x * blockDim.x + threadIdx.x;   // seg index
    size_t nseg = (size_t)NDIM * (KDIM / 8);
    if (i < nseg) {
        int n  = (int)(i >> 9);
        int sk = (int)(i & 511);
        int kc = sk >> 3;
        int seg = sk & 7;
        const int4* src = reinterpret_cast<const int4*>(w4 + (size_t)n * KDIM + sk * 8);
        int4 q0 = src[0], q1 = src[1];
        int z = __float2int_rn(zp[0]);    // zero_point is an exact integer
        uint4 o;
        o.x = h2_bits(__floats2half2_rn((float)(q0.x - z), (float)(q0.y - z)));
        o.y = h2_bits(__floats2half2_rn((float)(q0.z - z), (float)(q0.w - z)));
        o.z = h2_bits(__floats2half2_rn((float)(q1.x - z), (float)(q1.y - z)));
        o.w = h2_bits(__floats2half2_rn((float)(q1.z - z), (float)(q1.w - z)));
        size_t tile = (size_t)(n >> 7) * NCH + kc;
        uint32_t off = (uint32_t)(((n & 127) * 128 + seg * 16) ^ ((n & 7) << 4));
        *reinterpret_cast<uint4*>(
            reinterpret_cast<char*>(g_wh) + tile * TILE_BYTES + off) = o;
    }
}

// ---------------------------------------------------------------- GEMM
// Persistent kernel: 296 CTAs, each loops over tiles; the 3-stage bulk-copy
// ring runs continuously across tile boundaries (producer looks ahead 2
// chunks, crossing into the next tile during the current tile's tail).
__global__ void __launch_bounds__(NTHREADS, 2)
gemm_hmma_kernel(const float* __restrict__ scale, const float* __restrict__ bias,
                 float* __restrict__ out) {
    extern __shared__ char smem_raw[];
    char* sm = (char*)(((uintptr_t)smem_raw + 1023) & ~(uintptr_t)1023);
    uint32_t sb = smem_u32(sm);

    const int tid  = threadIdx.x;
    const int lane = tid & 31;
    const int wid  = tid >> 5;        // 0..3
    const int wm   = wid >> 1;        // 0..1  (64 M-rows per warp)
    const int wn   = wid & 1;         // 0..1  (64 N-cols per warp)
    const int bid  = blockIdx.x;

    const int nt = (TOT_TILES - bid + NCTA - 1) / NCTA;   // tiles for this CTA
    const long totc = (long)nt * NCH;                     // total chunks

    const uint32_t mb = sb + SM_MB;   // 3 mbarriers at mb, mb+8, mb+16
    if (tid == 0) {
        mbar_init(mb + 0, 1);
        mbar_init(mb + 8, 1);
        mbar_init(mb + 16, 1);
    }

    // ---- ldmatrix lane addressing (matches cvt-written swizzled layout) ----
    uint32_t cks[4];
#pragma unroll
    for (int ks = 0; ks < 4; ks++)
        cks[ks] = (uint32_t)((((lane >> 4) * 16) + ks * 32) ^ ((lane & 7) << 4));
    const uint32_t arow = (uint32_t)((wm * 64 + (lane & 15)) * 128);
    const uint32_t brow = (uint32_t)((wn * 64 + (lane & 15)) * 128);

    // tile id -> (bm, bn) panel swizzle (same locality as launched waves)
    auto map_tile = [](int t, int& bm, int& bn) {
        const int per_p = GROUP_M * GRID_N;
        const int panel = t / per_p;
        const int rem   = t - panel * per_p;
        bm = panel * GROUP_M + (rem % GROUP_M);
        bn = rem / GROUP_M;
    };

    __syncthreads();   // mbarrier init visible

    // ---- prologue: chunks 0,1 of first tile ----
    int bm0, bn0;
    map_tile(bid, bm0, bn0);
    const char* gA = reinterpret_cast<const char*>(g_xh) + (size_t)bm0 * NCH * TILE_BYTES;
    const char* gB = reinterpret_cast<const char*>(g_wh) + (size_t)bn0 * NCH * TILE_BYTES;
    if (tid == 0) {
        asm volatile("fence.proxy.async.shared::cta;" ::: "memory");
#pragma unroll
        for (int s = 0; s < 2; s++) {
            mbar_expect_tx(mb + 8 * s, 2 * TILE_BYTES);
            bulk_ld(sb + SM_A + s * TILE_BYTES, gA + (size_t)s * TILE_BYTES,
                    TILE_BYTES, mb + 8 * s);
            bulk_ld(sb + SM_B + s * TILE_BYTES, gB + (size_t)s * TILE_BYTES,
                    TILE_BYTES, mb + 8 * s);
        }
    }

    const float sc = *scale;
    int rs = 0, rph = 0;              // consumer stage / parity (continuous)
    long cs = 0;                      // global chunk counter

    for (int j = 0; j < nt; ++j) {
        const int t = bid + j * NCTA;
        int bm, bn;
        map_tile(t, bm, bn);
        const int m0 = bm * BM;
        const int n0 = bn * BN;

        // next tile's streams (for producer lookahead across the boundary)
        const char* ngA = gA;
        const char* ngB = gB;
        if (j + 1 < nt) {
            int nbm, nbn;
            map_tile(t + NCTA, nbm, nbn);
            ngA = reinterpret_cast<const char*>(g_xh) + (size_t)nbm * NCH * TILE_BYTES;
            ngB = reinterpret_cast<const char*>(g_wh) + (size_t)nbn * NCH * TILE_BYTES;
        }

        float c[4][8][4];
#pragma unroll
        for (int mi = 0; mi < 4; mi++)
#pragma unroll
            for (int ni = 0; ni < 8; ni++)
#pragma unroll
                for (int r = 0; r < 4; r++) c[mi][ni][r] = 0.0f;

        for (int k = 0; k < NCH; ++k) {
            if (cs > 0) __syncthreads();   // WAR: all reads of chunk cs-1 done
            if (tid == 0 && cs + 2 < totc) {
                int ws = rs + 2; if (ws >= STAGES) ws -= STAGES;
                const char *pa, *pb;
                const int pk2 = k + 2;
                if (pk2 < NCH) {
                    pa = gA + (size_t)pk2 * TILE_BYTES;
                    pb = gB + (size_t)pk2 * TILE_BYTES;
                } else {
                    pa = ngA + (size_t)(pk2 - NCH) * TILE_BYTES;
                    pb = ngB + (size_t)(pk2 - NCH) * TILE_BYTES;
                }
                asm volatile("fence.proxy.async.shared::cta;" ::: "memory");
                mbar_expect_tx(mb + 8 * ws, 2 * TILE_BYTES);
                bulk_ld(sb + SM_A + ws * TILE_BYTES, pa, TILE_BYTES, mb + 8 * ws);
                bulk_ld(sb + SM_B + ws * TILE_BYTES, pb, TILE_BYTES, mb + 8 * ws);
            }

            mbar_wait(mb + 8 * rs, (uint32_t)rph);   // chunk cs resident

            const uint32_t ab = sb + SM_A + rs * TILE_BYTES + arow;
            const uint32_t bb = sb + SM_B + rs * TILE_BYTES + brow;

            // fragment double-buffer: LDSM for step s+1 overlaps MMAs of step s
            uint32_t a[2][4][4], bf[2][4][4];
#pragma unroll
            for (int mi = 0; mi < 4; mi++) ldsm_x4(a[0][mi], ab + mi * 2048 + cks[0]);
#pragma unroll
            for (int nj = 0; nj < 4; nj++) ldsm_x4(bf[0][nj], bb + nj * 2048 + cks[0]);

#pragma unroll
            for (int ks = 0; ks < 4; ks++) {
                const int cur = ks & 1, nxt = cur ^ 1;
                if (ks < 3) {
#pragma unroll
                    for (int mi = 0; mi < 4; mi++)
                        ldsm_x4(a[nxt][mi], ab + mi * 2048 + cks[ks + 1]);
#pragma unroll
                    for (int nj = 0; nj < 4; nj++)
                        ldsm_x4(bf[nxt][nj], bb + nj * 2048 + cks[ks + 1]);
                }
#pragma unroll
                for (int mi = 0; mi < 4; mi++)
#pragma unroll
                    for (int nj = 0; nj < 4; nj++) {
                        mma16816(c[mi][2 * nj + 0], a[cur][mi], bf[cur][nj][0], bf[cur][nj][2]);
                        mma16816(c[mi][2 * nj + 1], a[cur][mi], bf[cur][nj][1], bf[cur][nj][3]);
                    }
            }

            ++cs;
            if (++rs == STAGES) { rs = 0; rph ^= 1; }
        }

        gA = ngA; gB = ngB;

        // ---- epilogue (overlaps the already-issued next-tile fills) ----
        const int qrow = lane >> 2;
        const int qcol = 2 * (lane & 3);
#pragma unroll
        for (int mi = 0; mi < 4; mi++) {
            const size_t mlo = (size_t)(m0 + wm * 64 + mi * 16 + qrow);
#pragma unroll
            for (int ni = 0; ni < 8; ni++) {
                const int nc = wn * 64 + ni * 8 + qcol;
                const float b0 = __ldg(&bias[n0 + nc]);
                const float b1 = __ldg(&bias[n0 + nc + 1]);
                float2 v0, v1;
                v0.x = fmaf(sc, c[mi][ni][0], b0);
                v0.y = fmaf(sc, c[mi][ni][1], b1);
                v1.x = fmaf(sc, c[mi][ni][2], b0);
                v1.y = fmaf(sc, c[mi][ni][3], b1);
                __stcs(reinterpret_cast<float2*>(out + mlo * NDIM + n0 + nc), v0);
                __stcs(reinterpret_cast<float2*>(out + (mlo + 8) * NDIM + n0 + nc), v1);
            }
        }
    }

    __syncthreads();
    if (tid == 0) {
        asm volatile("mbarrier.inval.shared.b64 [%0];" :: "r"(mb + 0) : "memory");
        asm volatile("mbarrier.inval.shared.b64 [%0];" :: "r"(mb + 8) : "memory");
        asm volatile("mbarrier.inval.shared.b64 [%0];" :: "r"(mb + 16) : "memory");
    }
}

// ---------------------------------------------------------------- launch
extern "C" void kernel_launch(void* const* d_in, const int* in_sizes, int n_in,
                              void* d_out, int out_size) {
    const float* x     = (const float*)d_in[0];
    const int*   w4    = (const int*)d_in[1];
    const float* scale = (const float*)d_in[2];
    const float* zp    = (const float*)d_in[3];
    const float* bias  = (const float*)d_in[4];
    float* out = (float*)d_out;

    cudaFuncSetAttribute(gemm_hmma_kernel,
                         cudaFuncAttributeMaxDynamicSharedMemorySize, DYN_SMEM);

    {
        long nseg = (long)MDIM * KDIM / 8;
        cvt_x_kernel<<<(int)((nseg + 255) / 256), 256>>>(x);
    }
    {
        long nseg = (long)NDIM * KDIM / 8;
        cvt_w_kernel<<<(int)((nseg + 255) / 256), 256>>>(w4, zp);
    }
    gemm_hmma_kernel<<<NCTA, NTHREADS, DYN_SMEM>>>(scale, bias, out);
}